// round 16
// baseline (speedup 1.0000x reference)
#include <cuda_runtime.h>
#include <cuda_bf16.h>
#include <math.h>
#include <stdint.h>

#define Bb 2
#define Cc 768
#define Tt 2048
#define Ii 768
#define Hh 12
#define Dh 64
#define Ss 16
#define Cx 512
#define Fi 3072
#define Dd 2
#define Ksz 9

typedef __nv_bfloat16 bf16;
typedef unsigned short u16;

// ---------------- scratch ----------------
__device__ float g_h  [(long long)Bb*Tt*Ii];
__device__ float g_q  [(long long)Bb*Tt*Ii];
__device__ float g_sc [(long long)Bb*Hh*Tt*Tt];
__device__ float g_kc [(long long)Bb*Ss*Ii];
__device__ float g_vc [(long long)Bb*Ss*Ii];

__device__ u16 g_gnh[(long long)Bb*Cc*Tt], g_gnl[(long long)Bb*Cc*Tt];  // TRANSPOSED [b][t][c]
__device__ u16 g_yh [(long long)Bb*Tt*Ii], g_yl [(long long)Bb*Tt*Ii];
__device__ u16 g_qkvh[(long long)Bb*Tt*3*Ii], g_qkvl[(long long)Bb*Tt*3*Ii];
__device__ u16 g_vth[(long long)Bb*Ii*Tt], g_vtl[(long long)Bb*Ii*Tt];
__device__ u16 g_ath[(long long)Bb*Tt*Ii], g_atl[(long long)Bb*Tt*Ii];
__device__ u16 g_hh [(long long)Bb*Tt*Ii], g_hl [(long long)Bb*Tt*Ii];
__device__ u16 g_ph [(long long)Bb*Hh*Tt*Tt], g_pl [(long long)Bb*Hh*Tt*Tt];
__device__ u16 g_ffh[(long long)Bb*Tt*Fi], g_ffl[(long long)Bb*Tt*Fi];
__device__ u16 g_w1h[(long long)Fi*Ii*Ksz], g_w1l[(long long)Fi*Ii*Ksz];
__device__ u16 g_w2h[(long long)Ii*Fi*Ksz], g_w2l[(long long)Ii*Fi*Ksz];
__device__ u16 g_wth[8ll*Ii*Ii], g_wtl[8ll*Ii*Ii];

// ---------------- helpers ----------------
__device__ __forceinline__ uint32_t smem_u32(const void* p) {
    uint32_t a;
    asm("{ .reg .u64 t; cvta.to.shared.u64 t, %1; cvt.u32.u64 %0, t; }" : "=r"(a) : "l"(p));
    return a;
}
#define SWZ(x) ((x) ^ ((((uint32_t)(x)) >> 3) & 0x70))
#define CP16(dst, src) asm volatile("cp.async.cg.shared.global [%0], [%1], 16;" :: "r"(dst), "l"(src))
#define CPCOMMIT() asm volatile("cp.async.commit_group;" ::: "memory")
#define CPWAIT0() asm volatile("cp.async.wait_group 0;" ::: "memory")

__device__ __forceinline__ void ldsm4(uint32_t* r, uint32_t addr) {
    asm volatile("ldmatrix.sync.aligned.m8n8.x4.shared.b16 {%0,%1,%2,%3}, [%4];"
        : "=r"(r[0]), "=r"(r[1]), "=r"(r[2]), "=r"(r[3]) : "r"(addr));
}
__device__ __forceinline__ void mma16816(float* c, const uint32_t* a, const uint32_t* b) {
    asm volatile("mma.sync.aligned.m16n8k16.row.col.f32.bf16.bf16.f32 "
        "{%0,%1,%2,%3}, {%4,%5,%6,%7}, {%8,%9}, {%0,%1,%2,%3};"
        : "+f"(c[0]), "+f"(c[1]), "+f"(c[2]), "+f"(c[3])
        : "r"(a[0]), "r"(a[1]), "r"(a[2]), "r"(a[3]), "r"(b[0]), "r"(b[1]));
}
__device__ __forceinline__ void splitf(float x, u16& h, u16& l) {
    bf16 hb = __float2bfloat16(x);
    bf16 lb = __float2bfloat16(x - __bfloat162float(hb));
    h = __bfloat16_as_ushort(hb);
    l = __bfloat16_as_ushort(lb);
}

// flags
#define FBN   4
#define FBM   8
#define FGELU 16
#define FADD  32
#define FOUT  64
#define FSPL  128

// stage 16B segments via cp.async (non-trans): op[r][k] = G[off0 + r*ld + k]
__device__ __forceinline__ void stage_nt(const u16* __restrict__ Gh, const u16* __restrict__ Gl,
        long long off0, long long flim, int ld, int k0, int rows,
        uint32_t smh, uint32_t sml) {
    int nseg = rows * 8;
    for (int idx = threadIdx.x; idx < nseg; idx += blockDim.x) {
        int r = idx >> 3, s = idx & 7;
        long long f = off0 + (long long)r * ld + k0 + s * 8;
        uint32_t d = SWZ((uint32_t)(r * 128 + s * 16));
        if (f >= 0 && f + 8 <= flim) {
            CP16(smh + d, Gh + f);
            CP16(sml + d, Gl + f);
        } else {
            asm volatile("st.shared.v4.u32 [%0], {%1,%1,%1,%1};" :: "r"(smh + d), "r"(0));
            asm volatile("st.shared.v4.u32 [%0], {%1,%1,%1,%1};" :: "r"(sml + d), "r"(0));
        }
    }
}

// ===== tensor-core GEMM, templated M-warps (NWM): tile (32*NWM) x 64 =====
// NWM=4: 256 thr, 2 CTAs/SM.  NWM=2: 128 thr, 3 CTAs/SM.  warp tile 32x32.
template<int NWM>
__global__ void __launch_bounds__(NWM * 64, (NWM == 4 ? 2 : 3))
tc_gemm(const u16* __restrict__ Ah, const u16* __restrict__ Al,
        const u16* __restrict__ Bh, const u16* __restrict__ Bl,
        const float* __restrict__ bias, float* __restrict__ out,
        u16* __restrict__ oh, u16* __restrict__ ol,
        int K, int lda, int ldb, long long ldo, int flags, float alpha,
        long long offA, long long flimA, int b2,
        long long sA1, long long sA2, long long sB1, long long sB2,
        long long sC1, long long sC2)
{
    extern __shared__ char dynsm[];
    long long z1 = blockIdx.z / b2, z2 = blockIdx.z % b2;
    Ah += z1 * sA1 + z2 * sA2;  Al += z1 * sA1 + z2 * sA2;
    Bh += z1 * sB1 + z2 * sB2;  Bl += z1 * sB1 + z2 * sB2;
    long long zc = z1 * sC1 + z2 * sC2;
    out += zc;
    if (flags & FSPL) { oh += zc; ol += zc; }

    const int tid = threadIdx.x;
    const int lane = tid & 31;
    const int wid = tid >> 5;
    const int wm = (wid % NWM) * 32;
    const int wn = (wid / NWM) * 32;
    const int ksrot = (wid / NWM) << 1;       // 0 / 2 phase stagger
    constexpr int MT = NWM * 32;
    const int m0 = blockIdx.y * MT;
    const int n0 = blockIdx.x * 64;
    constexpr int NTW = 4;
    constexpr int NB = 2;
    constexpr int AHALF = NWM * 4096;         // A hi bytes
    constexpr int ASZ = NWM * 8192;           // A hi+lo bytes
    constexpr int STG = ASZ + 16384;          // + B hi+lo

    uint32_t smBase = smem_u32(dynsm);
    smBase = (smBase + 1023) & ~1023u;

    const long long aoff = offA + (long long)m0 * lda;
    const long long boff = (long long)n0 * ldb;
    const long long BIGL = 1LL << 62;
    const int nc = K / 64;

    float acc[2][NTW][4];
    #pragma unroll
    for (int i = 0; i < 2; ++i)
        #pragma unroll
        for (int j = 0; j < NTW; ++j)
            #pragma unroll
            for (int l = 0; l < 4; ++l) acc[i][j][l] = 0.f;

    const uint32_t aRow = wm + (lane & 15);
    const uint32_t aKof = (lane >> 4) << 3;
    const int bi = lane >> 3;
    const uint32_t bRowBase = wn + ((bi >> 1) << 3) + (lane & 7);
    const uint32_t bKof = (bi & 1) << 3;

    auto stage = [&](int c, int s) {
        uint32_t base = smBase + s * STG;
        stage_nt(Ah, Al, aoff, flimA, lda, c * 64, MT, base, base + AHALF);
        stage_nt(Bh, Bl, boff, BIGL, ldb, c * 64, 64, base + ASZ, base + ASZ + 8192);
        CPCOMMIT();
    };

    stage(0, 0);
    CPWAIT0();
    __syncthreads();

    for (int c = 0; c < nc; ++c) {
        if (c + 1 < nc) stage(c + 1, (c + 1) & 1);
        uint32_t base = smBase + (c & 1) * STG;
        const uint32_t aHi = base, aLo = base + AHALF;
        const uint32_t bHi = base + ASZ, bLo = base + ASZ + 8192;
        #pragma unroll
        for (int ki = 0; ki < 4; ++ki) {
            const int ks = (ki + ksrot) & 3;
            const uint32_t kb = ks * 16;
            uint32_t ah[2][4], al[2][4], bh[NB][4], bl[NB][4];
            #pragma unroll
            for (int mt = 0; mt < 2; ++mt) {
                uint32_t off = SWZ((aRow + mt * 16) * 128 + (kb + aKof) * 2);
                ldsm4(ah[mt], aHi + off);
                ldsm4(al[mt], aLo + off);
            }
            #pragma unroll
            for (int bp = 0; bp < NB; ++bp) {
                uint32_t off = SWZ((bRowBase + bp * 16) * 128 + (kb + bKof) * 2);
                ldsm4(bh[bp], bHi + off);
                ldsm4(bl[bp], bLo + off);
            }
            #pragma unroll
            for (int bp = 0; bp < NB; ++bp)
                #pragma unroll
                for (int mt = 0; mt < 2; ++mt) {
                    mma16816(acc[mt][2 * bp],     ah[mt], bh[bp]);
                    mma16816(acc[mt][2 * bp + 1], ah[mt], bh[bp] + 2);
                }
            #pragma unroll
            for (int bp = 0; bp < NB; ++bp)
                #pragma unroll
                for (int mt = 0; mt < 2; ++mt) {
                    mma16816(acc[mt][2 * bp],     al[mt], bh[bp]);
                    mma16816(acc[mt][2 * bp + 1], al[mt], bh[bp] + 2);
                }
            #pragma unroll
            for (int bp = 0; bp < NB; ++bp)
                #pragma unroll
                for (int mt = 0; mt < 2; ++mt) {
                    mma16816(acc[mt][2 * bp],     ah[mt], bl[bp]);
                    mma16816(acc[mt][2 * bp + 1], ah[mt], bl[bp] + 2);
                }
        }
        if (c + 1 < nc) { CPWAIT0(); __syncthreads(); }
    }

    // epilogue
    const int g = lane >> 2, tg = lane & 3;
    #pragma unroll
    for (int mt = 0; mt < 2; ++mt) {
        #pragma unroll
        for (int hf = 0; hf < 2; ++hf) {
            int m = m0 + wm + mt * 16 + g + hf * 8;
            float bm = (flags & FBM) ? bias[m] : 0.f;
            long long rbase = (long long)m * ldo;
            #pragma unroll
            for (int nt = 0; nt < NTW; ++nt) {
                int n = n0 + wn + nt * 8 + tg * 2;
                float v0 = alpha * acc[mt][nt][hf * 2 + 0];
                float v1 = alpha * acc[mt][nt][hf * 2 + 1];
                if (flags & FBN) { v0 += bias[n]; v1 += bias[n + 1]; }
                else if (flags & FBM) { v0 += bm; v1 += bm; }
                if (flags & FGELU) {
                    v0 = 0.5f * v0 * (1.f + erff(v0 * 0.70710678118654752f));
                    v1 = 0.5f * v1 * (1.f + erff(v1 * 0.70710678118654752f));
                }
                if (flags & FADD) { v0 += out[rbase + n]; v1 += out[rbase + n + 1]; }
                if (flags & (FOUT | FADD)) { out[rbase + n] = v0; out[rbase + n + 1] = v1; }
                if (flags & FSPL) {
                    u16 h0, l0, h1, l1;
                    splitf(v0, h0, l0);
                    splitf(v1, h1, l1);
                    oh[rbase + n] = h0; ol[rbase + n] = l0;
                    oh[rbase + n + 1] = h1; ol[rbase + n + 1] = l1;
                }
            }
        }
    }
}

// ---------------- reductions ----------------
__device__ __forceinline__ float blockReduceSum(float v) {
    __shared__ float sm[32];
    int lane = threadIdx.x & 31, wid = threadIdx.x >> 5;
    #pragma unroll
    for (int o = 16; o; o >>= 1) v += __shfl_xor_sync(0xffffffffu, v, o);
    if (lane == 0) sm[wid] = v;
    __syncthreads();
    if (wid == 0) {
        int nw = (blockDim.x + 31) >> 5;
        v = (lane < nw) ? sm[lane] : 0.f;
        #pragma unroll
        for (int o = 16; o; o >>= 1) v += __shfl_xor_sync(0xffffffffu, v, o);
        if (lane == 0) sm[0] = v;
    }
    __syncthreads();
    float r = sm[0];
    __syncthreads();
    return r;
}
__device__ __forceinline__ float blockReduceMax(float v) {
    __shared__ float sm[32];
    int lane = threadIdx.x & 31, wid = threadIdx.x >> 5;
    #pragma unroll
    for (int o = 16; o; o >>= 1) v = fmaxf(v, __shfl_xor_sync(0xffffffffu, v, o));
    if (lane == 0) sm[wid] = v;
    __syncthreads();
    if (wid == 0) {
        int nw = (blockDim.x + 31) >> 5;
        v = (lane < nw) ? sm[lane] : -INFINITY;
        #pragma unroll
        for (int o = 16; o; o >>= 1) v = fmaxf(v, __shfl_xor_sync(0xffffffffu, v, o));
        if (lane == 0) sm[0] = v;
    }
    __syncthreads();
    float r = sm[0];
    __syncthreads();
    return r;
}

// groupnorm: writes split output TRANSPOSED: gnT[b][t][c]
__global__ void groupnorm_kernel(const float* __restrict__ x, const float* __restrict__ sc,
                                 const float* __restrict__ bi,
                                 u16* __restrict__ oh, u16* __restrict__ ol) {
    const int CPG = Cc / 32;
    int b = blockIdx.x >> 5, g = blockIdx.x & 31;
    const long long base = ((long long)b * Cc + (long long)g * CPG) * Tt;
    const float* xp = x + base;
    const int n = CPG * Tt;
    float s = 0.f, ss = 0.f;
    for (int i = threadIdx.x; i < n; i += blockDim.x) {
        float v = xp[i]; s += v; ss = fmaf(v, v, ss);
    }
    s = blockReduceSum(s); ss = blockReduceSum(ss);
    float mean = s / n;
    float inv = rsqrtf(ss / n - mean * mean + 1e-6f);
    const long long obase = (long long)b * Tt * Cc + g * CPG;
    for (int j = threadIdx.x; j < n; j += blockDim.x) {
        int t = j / CPG, cc2 = j - t * CPG;
        float v = (xp[(long long)cc2 * Tt + t] - mean) * inv * sc[g * CPG + cc2] + bi[g * CPG + cc2];
        u16 hv, lv; splitf(v, hv, lv);
        long long o = obase + (long long)t * Cc + cc2;
        oh[o] = hv; ol[o] = lv;
    }
}

__global__ void layernorm_kernel(const float* __restrict__ x, const float* __restrict__ sc,
                                 const float* __restrict__ bi,
                                 u16* __restrict__ oh, u16* __restrict__ ol) {
    const long long rb = (long long)blockIdx.x * Ii;
    const float* row = x + rb;
    float s = 0.f, ss = 0.f;
    for (int i = threadIdx.x; i < Ii; i += blockDim.x) {
        float v = row[i]; s += v; ss = fmaf(v, v, ss);
    }
    s = blockReduceSum(s); ss = blockReduceSum(ss);
    float mean = s / (float)Ii;
    float inv = rsqrtf(ss / (float)Ii - mean * mean + 1e-5f);
    for (int i = threadIdx.x; i < Ii; i += blockDim.x) {
        float v = (row[i] - mean) * inv * sc[i] + bi[i];
        u16 hv, lv; splitf(v, hv, lv);
        oh[rb + i] = hv; ol[rb + i] = lv;
    }
}

// small fp32 gemm for tiny cross-attn K/V projections (M=32)
__global__ void __launch_bounds__(256) gemm_kernel(
    const float* __restrict__ A, const float* __restrict__ B, float* __restrict__ Cp,
    int M, int N, int K, int lda, int ldb, int ldc)
{
    __shared__ float As[16][65];
    __shared__ float Bs[16][65];
    int n0 = blockIdx.x * 64, m0 = blockIdx.y * 64;
    int tid = threadIdx.x;
    int tx = tid & 15, ty = tid >> 4;
    float acc[4][4] = {};
    for (int k0 = 0; k0 < K; k0 += 16) {
        #pragma unroll
        for (int u = 0; u < 4; ++u) {
            int i = tid + u * 256;
            int mm = i >> 4, kk = i & 15;
            int m = m0 + mm, k = k0 + kk;
            As[kk][mm] = (m < M && k < K) ? A[(long long)m * lda + k] : 0.f;
        }
        #pragma unroll
        for (int u = 0; u < 4; ++u) {
            int i = tid + u * 256;
            int kk = i >> 6, nn = i & 63;
            int k = k0 + kk, n = n0 + nn;
            Bs[kk][nn] = (k < K && n < N) ? B[(long long)k * ldb + n] : 0.f;
        }
        __syncthreads();
        #pragma unroll
        for (int kk = 0; kk < 16; ++kk) {
            float a[4], bb[4];
            #pragma unroll
            for (int i = 0; i < 4; ++i) a[i] = As[kk][ty * 4 + i];
            #pragma unroll
            for (int j = 0; j < 4; ++j) bb[j] = Bs[kk][tx * 4 + j];
            #pragma unroll
            for (int i = 0; i < 4; ++i)
                #pragma unroll
                for (int j = 0; j < 4; ++j)
                    acc[i][j] = fmaf(a[i], bb[j], acc[i][j]);
        }
        __syncthreads();
    }
    #pragma unroll
    for (int i = 0; i < 4; ++i) {
        int m = m0 + ty * 4 + i;
        if (m >= M) continue;
        #pragma unroll
        for (int j = 0; j < 4; ++j) {
            int n = n0 + tx * 4 + j;
            if (n < N) Cp[(long long)m * ldc + n] = acc[i][j];
        }
    }
}

__global__ void softmax_kernel(const float* __restrict__ s,
                               u16* __restrict__ oh, u16* __restrict__ ol) {
    const long long rb = (long long)blockIdx.x * Tt;
    const float* row = s + rb;
    int tid = threadIdx.x;
    float v[8];
    float mx = -INFINITY;
    #pragma unroll
    for (int i = 0; i < 8; ++i) { v[i] = row[tid + (i << 8)]; mx = fmaxf(mx, v[i]); }
    mx = blockReduceMax(mx);
    float sum = 0.f;
    #pragma unroll
    for (int i = 0; i < 8; ++i) { v[i] = expf(v[i] - mx); sum += v[i]; }
    sum = blockReduceSum(sum);
    float inv = 1.f / sum;
    #pragma unroll
    for (int i = 0; i < 8; ++i) {
        u16 hv, lv; splitf(v[i] * inv, hv, lv);
        oh[rb + tid + (i << 8)] = hv;
        ol[rb + tid + (i << 8)] = lv;
    }
}

__global__ void crossattn_kernel(const float* __restrict__ q, const float* __restrict__ kc,
                                 const float* __restrict__ vc,
                                 u16* __restrict__ oh, u16* __restrict__ ol) {
    int gw = blockIdx.x * (blockDim.x >> 5) + (threadIdx.x >> 5);
    int lane = threadIdx.x & 31;
    int t = gw % Tt;
    int rem = gw / Tt;
    int h = rem % Hh;
    int b = rem / Hh;
    const float* qp = q + ((long long)(b * Tt + t)) * Ii + h * Dh;
    const float* kb = kc + (long long)b * Ss * Ii + h * Dh;
    const float* vb = vc + (long long)b * Ss * Ii + h * Dh;
    float sj = -INFINITY;
    if (lane < Ss) {
        const float* kp = kb + lane * Ii;
        float acc = 0.f;
        #pragma unroll
        for (int d2 = 0; d2 < Dh; ++d2) acc = fmaf(qp[d2], kp[d2], acc);
        sj = acc * 0.125f;
    }
    float mx = sj;
    #pragma unroll
    for (int o = 16; o; o >>= 1) mx = fmaxf(mx, __shfl_xor_sync(0xffffffffu, mx, o));
    float p = (lane < Ss) ? expf(sj - mx) : 0.f;
    float sum = p;
    #pragma unroll
    for (int o = 16; o; o >>= 1) sum += __shfl_xor_sync(0xffffffffu, sum, o);
    p /= sum;
    float o0 = 0.f, o1 = 0.f;
    #pragma unroll
    for (int j = 0; j < Ss; ++j) {
        float pj = __shfl_sync(0xffffffffu, p, j);
        const float* vp = vb + j * Ii;
        o0 = fmaf(pj, vp[lane], o0);
        o1 = fmaf(pj, vp[lane + 32], o1);
    }
    long long ob = ((long long)(b * Tt + t)) * Ii + h * Dh;
    u16 hv, lv;
    splitf(o0, hv, lv); oh[ob + lane] = hv; ol[ob + lane] = lv;
    splitf(o1, hv, lv); oh[ob + lane + 32] = hv; ol[ob + lane + 32] = lv;
}

// per-head transpose of split V (src row stride ld, col offset off)
__global__ void transposeV_kernel(const u16* __restrict__ vh, const u16* __restrict__ vl,
                                  u16* __restrict__ oth, u16* __restrict__ otl,
                                  int ld, int off) {
    __shared__ u16 th[32][33], tl[32][33];
    int bh = blockIdx.z;
    int b = bh / Hh, h = bh % Hh;
    int t0 = blockIdx.x * 32, d0 = blockIdx.y * 32;
    #pragma unroll
    for (int i = 0; i < 32; i += 8) {
        long long src = ((long long)(b * Tt + t0 + threadIdx.y + i)) * ld + off + h * Dh + d0 + threadIdx.x;
        th[threadIdx.y + i][threadIdx.x] = vh[src];
        tl[threadIdx.y + i][threadIdx.x] = vl[src];
    }
    __syncthreads();
    #pragma unroll
    for (int i = 0; i < 32; i += 8) {
        long long dst = ((long long)((b * Hh + h) * Dh + d0 + threadIdx.y + i)) * Tt + t0 + threadIdx.x;
        oth[dst] = th[threadIdx.x][threadIdx.y + i];
        otl[dst] = tl[threadIdx.x][threadIdx.y + i];
    }
}

// elementwise split fp32 -> bf16 hi/lo
__global__ void split_ew(const float* __restrict__ w, u16* __restrict__ oh,
                         u16* __restrict__ ol, long long n) {
    long long i = (long long)blockIdx.x * 256 + threadIdx.x;
    if (i >= n) return;
    u16 hv, lv; splitf(w[i], hv, lv);
    oh[i] = hv; ol[i] = lv;
}

// transpose 768x768 [K][N] -> [N][K] + split
__global__ void splitT768(const float* __restrict__ w, u16* __restrict__ oh,
                          u16* __restrict__ ol) {
    __shared__ float t[32][33];
    int k0 = blockIdx.y * 32, n0 = blockIdx.x * 32;
    #pragma unroll
    for (int i = 0; i < 32; i += 8)
        t[threadIdx.y + i][threadIdx.x] = w[(long long)(k0 + threadIdx.y + i) * Ii + n0 + threadIdx.x];
    __syncthreads();
    #pragma unroll
    for (int i = 0; i < 32; i += 8) {
        long long o = (long long)(n0 + threadIdx.y + i) * Ii + k0 + threadIdx.x;
        u16 hv, lv; splitf(t[threadIdx.x][threadIdx.y + i], hv, lv);
        oh[o] = hv; ol[o] = lv;
    }
}

// conv weight reorder+split: out[o][k*Cin+c] = in[o][c*Ksz+k]
__global__ void reorder_split(const float* __restrict__ w, u16* __restrict__ oh,
                              u16* __restrict__ ol, long long total, int Cin) {
    long long i = (long long)blockIdx.x * 256 + threadIdx.x;
    if (i >= total) return;
    int rk = Cin * Ksz;
    long long oc = i / rk;
    int r = (int)(i - oc * rk);
    int k = r / Cin, c = r - k * Cin;
    u16 hv, lv; splitf(w[oc * rk + (long long)c * Ksz + k], hv, lv);
    oh[i] = hv; ol[i] = lv;
}

// ---------------- host wrapper ----------------
#define SMEM_M128 (2 * (32768 + 16384) + 1024)
#define SMEM_M64  (2 * (16384 + 16384) + 1024)

static void tc(int mt, const u16* Ah, const u16* Al, const u16* Bh, const u16* Bl,
               const float* bias, float* out, u16* oh, u16* ol,
               int gx, int gy, int gz, int K, int lda, int ldb, long long ldo,
               int flags, float alpha, long long offA, long long flimA,
               int b2, long long sA1, long long sA2, long long sB1, long long sB2,
               long long sC1, long long sC2)
{
    dim3 g(gx, gy, gz);
    if (mt == 64)
        tc_gemm<2><<<g, 128, SMEM_M64>>>(Ah, Al, Bh, Bl, bias, out, oh, ol, K, lda, ldb,
            ldo, flags, alpha, offA, flimA, b2, sA1, sA2, sB1, sB2, sC1, sC2);
    else
        tc_gemm<4><<<g, 256, SMEM_M128>>>(Ah, Al, Bh, Bl, bias, out, oh, ol, K, lda, ldb,
            ldo, flags, alpha, offA, flimA, b2, sA1, sA2, sB1, sB2, sC1, sC2);
}

extern "C" void kernel_launch(void* const* d_in, const int* in_sizes, int n_in,
                              void* d_out, int out_size) {
    const float* x      = (const float*)d_in[0];
    const float* ctx    = (const float*)d_in[1];
    const float* gn_s   = (const float*)d_in[2];
    const float* gn_b   = (const float*)d_in[3];
    const float* pin_w  = (const float*)d_in[4];
    const float* pin_b  = (const float*)d_in[5];
    const float* n1_s   = (const float*)d_in[6];
    const float* n1_b   = (const float*)d_in[7];
    const float* a1_wq  = (const float*)d_in[8];
    const float* a1_wk  = (const float*)d_in[9];
    const float* a1_wv  = (const float*)d_in[10];
    const float* a1_wo  = (const float*)d_in[11];
    const float* a1_bo  = (const float*)d_in[12];
    const float* n2_s   = (const float*)d_in[13];
    const float* n2_b   = (const float*)d_in[14];
    const float* a2_wq  = (const float*)d_in[15];
    const float* a2_wk  = (const float*)d_in[16];
    const float* a2_wv  = (const float*)d_in[17];
    const float* a2_wo  = (const float*)d_in[18];
    const float* a2_bo  = (const float*)d_in[19];
    const float* n3_s   = (const float*)d_in[20];
    const float* n3_b   = (const float*)d_in[21];
    const float* ff1_w  = (const float*)d_in[22];
    const float* ff1_b  = (const float*)d_in[23];
    const float* ff2_w  = (const float*)d_in[24];
    const float* ff2_b  = (const float*)d_in[25];
    const float* pout_w = (const float*)d_in[26];
    const float* pout_b = (const float*)d_in[27];
    float* out = (float*)d_out;

    cudaFuncSetAttribute(tc_gemm<4>, cudaFuncAttributeMaxDynamicSharedMemorySize, SMEM_M128);
    cudaFuncSetAttribute(tc_gemm<2>, cudaFuncAttributeMaxDynamicSharedMemorySize, SMEM_M64);

    float *h, *q, *sc, *kcb, *vcb;
    u16 *gnh, *gnl, *yh, *yl, *qkvh, *qkvl, *vth_, *vtl_, *ath, *atl;
    u16 *hh, *hl, *ph, *pl, *ffh, *ffl, *w1h, *w1l, *w2h, *w2l, *wth, *wtl;
    cudaGetSymbolAddress((void**)&h,   g_h);
    cudaGetSymbolAddress((void**)&q,   g_q);
    cudaGetSymbolAddress((void**)&sc,  g_sc);
    cudaGetSymbolAddress((void**)&kcb, g_kc);
    cudaGetSymbolAddress((void**)&vcb, g_vc);
    cudaGetSymbolAddress((void**)&gnh, g_gnh); cudaGetSymbolAddress((void**)&gnl, g_gnl);
    cudaGetSymbolAddress((void**)&yh,  g_yh);  cudaGetSymbolAddress((void**)&yl,  g_yl);
    cudaGetSymbolAddress((void**)&qkvh, g_qkvh); cudaGetSymbolAddress((void**)&qkvl, g_qkvl);
    cudaGetSymbolAddress((void**)&vth_, g_vth); cudaGetSymbolAddress((void**)&vtl_, g_vtl);
    cudaGetSymbolAddress((void**)&ath, g_ath); cudaGetSymbolAddress((void**)&atl, g_atl);
    cudaGetSymbolAddress((void**)&hh,  g_hh);  cudaGetSymbolAddress((void**)&hl,  g_hl);
    cudaGetSymbolAddress((void**)&ph,  g_ph);  cudaGetSymbolAddress((void**)&pl,  g_pl);
    cudaGetSymbolAddress((void**)&ffh, g_ffh); cudaGetSymbolAddress((void**)&ffl, g_ffl);
    cudaGetSymbolAddress((void**)&w1h, g_w1h); cudaGetSymbolAddress((void**)&w1l, g_w1l);
    cudaGetSymbolAddress((void**)&w2h, g_w2h); cudaGetSymbolAddress((void**)&w2l, g_w2l);
    cudaGetSymbolAddress((void**)&wth, g_wth); cudaGetSymbolAddress((void**)&wtl, g_wtl);

    const long long BIG = 1LL << 62;
    const long long TI = (long long)Tt * Ii;
    const long long T3I = (long long)Tt * 3 * Ii;
    const long long WSZ = (long long)Ii * Ii;
    const unsigned WB = (unsigned)((WSZ + 255) / 256);

    split_ew<<<WB, 256>>>(pin_w,  wth + 6 * WSZ, wtl + 6 * WSZ, WSZ);
    split_ew<<<WB, 256>>>(pout_w, wth + 7 * WSZ, wtl + 7 * WSZ, WSZ);

    groupnorm_kernel<<<Bb * 32, 256>>>(x, gn_s, gn_b, gnh, gnl);  // writes gnT [b][t][c]

    // proj_in (M64: 12 x 32 x 2 = 768 blocks)
    tc(64, gnh, gnl, wth + 6 * WSZ, wtl + 6 * WSZ, pin_b, h, 0, 0,
       Ii / 64, Tt / 64, Bb, Cc, Cc, Cc, Ii, FBN | FOUT, 1.f,
       0, BIG, 1, (long long)Tt * Cc, 0, 0, 0, TI, 0);

    for (int d = 0; d < Dd; ++d) {
        long long wofs = (long long)d * WSZ;
        dim3 tg(24, 24), tb(32, 8);
        splitT768<<<tg, tb>>>(a1_wq + wofs, wth + 0 * WSZ, wtl + 0 * WSZ);
        splitT768<<<tg, tb>>>(a1_wk + wofs, wth + 1 * WSZ, wtl + 1 * WSZ);
        splitT768<<<tg, tb>>>(a1_wv + wofs, wth + 2 * WSZ, wtl + 2 * WSZ);
        splitT768<<<tg, tb>>>(a1_wo + wofs, wth + 3 * WSZ, wtl + 3 * WSZ);
        splitT768<<<tg, tb>>>(a2_wq + wofs, wth + 4 * WSZ, wtl + 4 * WSZ);
        splitT768<<<tg, tb>>>(a2_wo + wofs, wth + 5 * WSZ, wtl + 5 * WSZ);
        {
            long long t1 = (long long)Fi * Ii * Ksz;
            reorder_split<<<(unsigned)((t1 + 255) / 256), 256>>>(ff1_w + d * t1, w1h, w1l, t1, Ii);
            long long t2 = (long long)Ii * Fi * Ksz;
            reorder_split<<<(unsigned)((t2 + 255) / 256), 256>>>(ff2_w + d * t2, w2h, w2l, t2, Fi);
        }

        // --- self attention ---
        layernorm_kernel<<<Bb * Tt, 256>>>(h, n1_s + d * Ii, n1_b + d * Ii, yh, yl);
        // fused QKV (M128: 36 x 32 = 1152 blocks)
        tc(128, yh, yl, wth, wtl, 0, sc, qkvh, qkvl, (3 * Ii) / 64, (Bb * Tt) / 128, 1,
           Ii, Ii, Ii, 3 * Ii, FSPL, 1.f, 0, BIG, 1, 0, 0, 0, 0, 0, 0);
        {
            dim3 g(Tt / 32, Dh / 32, Bb * Hh);
            transposeV_kernel<<<g, dim3(32, 8)>>>(qkvh, qkvl, vth_, vtl_, 3 * Ii, 2 * Ii);
        }
        // scores (M128: 32 x 16 x 24 = 12288 blocks)
        tc(128, qkvh, qkvl, qkvh + Ii, qkvl + Ii, 0, sc, 0, 0,
           Tt / 64, Tt / 128, Bb * Hh, Dh, 3 * Ii, 3 * Ii, Tt,
           FOUT, 0.125f, 0, BIG, Hh, T3I, Dh, T3I, Dh,
           (long long)Hh * Tt * Tt, (long long)Tt * Tt);
        softmax_kernel<<<Bb * Hh * Tt, 256>>>(sc, ph, pl);
        // att = P @ V (M64: 1 x 32 x 24 = 768 blocks)
        tc(64, ph, pl, vth_, vtl_, 0, sc, ath, atl, 1, Tt / 64, Bb * Hh, Tt, Tt, Tt, Ii,
           FSPL, 1.f, 0, BIG, Hh,
           (long long)Hh * Tt * Tt, (long long)Tt * Tt,
           (long long)Hh * Dh * Tt, (long long)Dh * Tt, TI, Dh);
        // h += att @ wo + bo (M64: 12 x 64 = 768 blocks)
        tc(64, ath, atl, wth + 3 * WSZ, wtl + 3 * WSZ, a1_bo + d * Ii, h, 0, 0,
           Ii / 64, (Bb * Tt) / 64, 1, Ii, Ii, Ii, Ii,
           FBN | FADD, 1.f, 0, BIG, 1, 0, 0, 0, 0, 0, 0);

        // --- cross attention ---
        layernorm_kernel<<<Bb * Tt, 256>>>(h, n2_s + d * Ii, n2_b + d * Ii, yh, yl);
        tc(64, yh, yl, wth + 4 * WSZ, wtl + 4 * WSZ, 0, q, 0, 0, Ii / 64, (Bb * Tt) / 64, 1,
           Ii, Ii, Ii, Ii, FOUT, 1.f, 0, BIG, 1, 0, 0, 0, 0, 0, 0);
        {
            dim3 g((Ii + 63) / 64, (Bb * Ss + 63) / 64);
            gemm_kernel<<<g, 256>>>(ctx, a2_wk + (long long)d * Cx * Ii, kcb,
                                    Bb * Ss, Ii, Cx, Cx, Ii, Ii);
            gemm_kernel<<<g, 256>>>(ctx, a2_wv + (long long)d * Cx * Ii, vcb,
                                    Bb * Ss, Ii, Cx, Cx, Ii, Ii);
        }
        crossattn_kernel<<<Bb * Hh * Tt / 8, 256>>>(q, kcb, vcb, ath, atl);
        tc(64, ath, atl, wth + 5 * WSZ, wtl + 5 * WSZ, a2_bo + d * Ii, h, 0, 0,
           Ii / 64, (Bb * Tt) / 64, 1, Ii, Ii, Ii, Ii,
           FBN | FADD, 1.f, 0, BIG, 1, 0, 0, 0, 0, 0, 0);

        // --- feed-forward ---
        layernorm_kernel<<<Bb * Tt, 256>>>(h, n3_s + d * Ii, n3_b + d * Ii, yh, yl);
        // conv1 (M128: 48 x 16 x 2 = 1536 blocks)
        tc(128, yh, yl, w1h, w1l, ff1_b + d * Fi, sc, ffh, ffl, Fi / 64, Tt / 128, Bb,
           Ii * Ksz, Ii, Ii * Ksz, Fi, FBN | FGELU | FSPL, 1.f,
           -(long long)4 * Ii, TI, 1, TI, 0, 0, 0, (long long)Tt * Fi, 0);
        // conv2 (M64: 12 x 32 x 2 = 768 blocks)
        tc(64, ffh, ffl, w2h, w2l, ff2_b + d * Ii, h, hh, hl, Ii / 64, Tt / 64, Bb,
           Fi * Ksz, Fi, Fi * Ksz, Ii,
           FBN | FADD | (d == Dd - 1 ? FSPL : 0), 1.f,
           -(long long)4 * Fi, (long long)Tt * Fi, 1,
           (long long)Tt * Fi, 0, 0, 0, TI, 0);
    }

    // out = x + pout_w @ h^T + pout_b (M64: 32 x 12 x 2 = 768 blocks)
    cudaMemcpyAsync(out, x, (size_t)Bb * Cc * Tt * sizeof(float),
                    cudaMemcpyDeviceToDevice);
    tc(64, wth + 7 * WSZ, wtl + 7 * WSZ, hh, hl, pout_b, out, 0, 0,
       Tt / 64, Cc / 64, Bb, Ii, Ii, Ii, Tt, FBM | FADD, 1.f,
       0, BIG, 1, 0, 0, TI, 0, (long long)Cc * Tt, 0);
}

// round 17
// speedup vs baseline: 1.0330x; 1.0330x over previous
#include <cuda_runtime.h>
#include <cuda_bf16.h>
#include <math.h>
#include <stdint.h>

#define Bb 2
#define Cc 768
#define Tt 2048
#define Ii 768
#define Hh 12
#define Dh 64
#define Ss 16
#define Cx 512
#define Fi 3072
#define Dd 2
#define Ksz 9

typedef __nv_bfloat16 bf16;
typedef unsigned short u16;

// ---------------- scratch ----------------
__device__ float g_h  [(long long)Bb*Tt*Ii];
__device__ float g_q  [(long long)Bb*Tt*Ii];
__device__ float g_sc [(long long)Bb*Hh*Tt*Tt];
__device__ float g_kc [(long long)Bb*Ss*Ii];
__device__ float g_vc [(long long)Bb*Ss*Ii];

__device__ u16 g_gnh[(long long)Bb*Cc*Tt], g_gnl[(long long)Bb*Cc*Tt];  // TRANSPOSED [b][t][c]
__device__ u16 g_yh [(long long)Bb*Tt*Ii], g_yl [(long long)Bb*Tt*Ii];
__device__ u16 g_qkvh[(long long)Bb*Tt*3*Ii], g_qkvl[(long long)Bb*Tt*3*Ii];
__device__ u16 g_vth[(long long)Bb*Ii*Tt], g_vtl[(long long)Bb*Ii*Tt];
__device__ u16 g_ath[(long long)Bb*Tt*Ii], g_atl[(long long)Bb*Tt*Ii];
__device__ u16 g_hh [(long long)Bb*Tt*Ii], g_hl [(long long)Bb*Tt*Ii];
__device__ u16 g_ph [(long long)Bb*Hh*Tt*Tt], g_pl [(long long)Bb*Hh*Tt*Tt];
__device__ u16 g_ffh[(long long)Bb*Tt*Fi], g_ffl[(long long)Bb*Tt*Fi];
__device__ u16 g_w1h[(long long)Fi*Ii*Ksz], g_w1l[(long long)Fi*Ii*Ksz];
__device__ u16 g_w2h[(long long)Ii*Fi*Ksz], g_w2l[(long long)Ii*Fi*Ksz];
__device__ u16 g_wth[8ll*Ii*Ii], g_wtl[8ll*Ii*Ii];

// ---------------- helpers ----------------
__device__ __forceinline__ uint32_t smem_u32(const void* p) {
    uint32_t a;
    asm("{ .reg .u64 t; cvta.to.shared.u64 t, %1; cvt.u32.u64 %0, t; }" : "=r"(a) : "l"(p));
    return a;
}
#define SWZ(x) ((x) ^ ((((uint32_t)(x)) >> 3) & 0x70))
#define CP16(dst, src) asm volatile("cp.async.cg.shared.global [%0], [%1], 16;" :: "r"(dst), "l"(src))
#define CPCOMMIT() asm volatile("cp.async.commit_group;" ::: "memory")
#define CPWAIT0() asm volatile("cp.async.wait_group 0;" ::: "memory")

__device__ __forceinline__ void ldsm4(uint32_t* r, uint32_t addr) {
    asm volatile("ldmatrix.sync.aligned.m8n8.x4.shared.b16 {%0,%1,%2,%3}, [%4];"
        : "=r"(r[0]), "=r"(r[1]), "=r"(r[2]), "=r"(r[3]) : "r"(addr));
}
__device__ __forceinline__ void mma16816(float* c, const uint32_t* a, const uint32_t* b) {
    asm volatile("mma.sync.aligned.m16n8k16.row.col.f32.bf16.bf16.f32 "
        "{%0,%1,%2,%3}, {%4,%5,%6,%7}, {%8,%9}, {%0,%1,%2,%3};"
        : "+f"(c[0]), "+f"(c[1]), "+f"(c[2]), "+f"(c[3])
        : "r"(a[0]), "r"(a[1]), "r"(a[2]), "r"(a[3]), "r"(b[0]), "r"(b[1]));
}
__device__ __forceinline__ void splitf(float x, u16& h, u16& l) {
    bf16 hb = __float2bfloat16(x);
    bf16 lb = __float2bfloat16(x - __bfloat162float(hb));
    h = __bfloat16_as_ushort(hb);
    l = __bfloat16_as_ushort(lb);
}

// flags
#define FBN   4
#define FBM   8
#define FGELU 16
#define FADD  32
#define FOUT  64
#define FSPL  128

#define NTHREADS 256
// stage: A 32KB (hi+lo) + B 16KB (hi+lo) = 48KB; 2 stages = 96KB
#define STG_BYTES (49152)
#define TC_SMEM (2*STG_BYTES + 1024)

// stage 16B segments via cp.async (non-trans): op[r][k] = G[off0 + r*ld + k]
__device__ __forceinline__ void stage_nt(const u16* __restrict__ Gh, const u16* __restrict__ Gl,
        long long off0, long long flim, int ld, int k0, int rows,
        uint32_t smh, uint32_t sml, bool chk) {
    int nseg = rows * 8;
    if (!chk) {
        for (int idx = threadIdx.x; idx < nseg; idx += NTHREADS) {
            int r = idx >> 3, s = idx & 7;
            long long f = off0 + (long long)r * ld + k0 + s * 8;
            uint32_t d = SWZ((uint32_t)(r * 128 + s * 16));
            CP16(smh + d, Gh + f);
            CP16(sml + d, Gl + f);
        }
    } else {
        for (int idx = threadIdx.x; idx < nseg; idx += NTHREADS) {
            int r = idx >> 3, s = idx & 7;
            long long f = off0 + (long long)r * ld + k0 + s * 8;
            uint32_t d = SWZ((uint32_t)(r * 128 + s * 16));
            if (f >= 0 && f + 8 <= flim) {
                CP16(smh + d, Gh + f);
                CP16(sml + d, Gl + f);
            } else {
                asm volatile("st.shared.v4.u32 [%0], {%1,%1,%1,%1};" :: "r"(smh + d), "r"(0));
                asm volatile("st.shared.v4.u32 [%0], {%1,%1,%1,%1};" :: "r"(sml + d), "r"(0));
            }
        }
    }
}

// ===== tensor-core GEMM: 256 threads, 4x2 warp grid, 2-stage, 2 CTAs/SM =====
// tile 128 x 64, warp tile 32 x 32. terms: 3 = full split, 2 = skip A-lo term.
__global__ void __launch_bounds__(NTHREADS, 2)
tc_gemm(const u16* __restrict__ Ah, const u16* __restrict__ Al,
        const u16* __restrict__ Bh, const u16* __restrict__ Bl,
        const float* __restrict__ bias, float* __restrict__ out,
        u16* __restrict__ oh, u16* __restrict__ ol,
        int K, int lda, int ldb, long long ldo, int flags, float alpha,
        long long offA, long long flimA, int b2,
        long long sA1, long long sA2, long long sB1, long long sB2,
        long long sC1, long long sC2, int terms)
{
    extern __shared__ char dynsm[];
    long long z1 = blockIdx.z / b2, z2 = blockIdx.z % b2;
    Ah += z1 * sA1 + z2 * sA2;  Al += z1 * sA1 + z2 * sA2;
    Bh += z1 * sB1 + z2 * sB2;  Bl += z1 * sB1 + z2 * sB2;
    long long zc = z1 * sC1 + z2 * sC2;
    out += zc;
    if (flags & FSPL) { oh += zc; ol += zc; }

    const int tid = threadIdx.x;
    const int lane = tid & 31;
    const int wid = tid >> 5;                 // 0..7
    const int wm = (wid & 3) * 32;            // 4 M-warps
    const int wn = (wid >> 2) * 32;           // 2 N-warps
    const int ksrot = (wid >> 2) << 1;        // phase stagger (0 / 2)
    const int m0 = blockIdx.y * 128;
    const int n0 = blockIdx.x * 64;
    constexpr int NTW = 4;                    // n8 tiles per warp
    constexpr int NB = 2;                     // 16-col pairs
    constexpr int ASZ = 32768;                // A hi+lo bytes

    uint32_t smBase = smem_u32(dynsm);
    smBase = (smBase + 1023) & ~1023u;

    const long long BIGL = 1LL << 62;
    const bool chkA = (flimA != BIGL);
    const long long aoff = offA + (long long)m0 * lda;
    const long long boff = (long long)n0 * ldb;
    const bool t3 = (terms == 3);
    const int nc = K / 64;

    float acc[2][NTW][4];
    #pragma unroll
    for (int i = 0; i < 2; ++i)
        #pragma unroll
        for (int j = 0; j < NTW; ++j)
            #pragma unroll
            for (int l = 0; l < 4; ++l) acc[i][j][l] = 0.f;

    const uint32_t aRow = wm + (lane & 15);
    const uint32_t aKof = (lane >> 4) << 3;
    const int bi = lane >> 3;
    const uint32_t bRowBase = wn + ((bi >> 1) << 3) + (lane & 7);
    const uint32_t bKof = (bi & 1) << 3;

    auto stage = [&](int c, int s) {
        uint32_t base = smBase + s * STG_BYTES;
        stage_nt(Ah, Al, aoff, flimA, lda, c * 64, 128, base, base + 16384, chkA);
        stage_nt(Bh, Bl, boff, BIGL, ldb, c * 64, 64, base + ASZ, base + ASZ + 8192, false);
        CPCOMMIT();
    };

    // prologue: chunk 0
    stage(0, 0);
    CPWAIT0();
    __syncthreads();

    for (int c = 0; c < nc; ++c) {
        if (c + 1 < nc) stage(c + 1, (c + 1) & 1);   // issued at top, waited at bottom
        uint32_t base = smBase + (c & 1) * STG_BYTES;
        const uint32_t aHi = base, aLo = base + 16384;
        const uint32_t bHi = base + ASZ, bLo = base + ASZ + 8192;
        #pragma unroll
        for (int ki = 0; ki < 4; ++ki) {
            const int ks = (ki + ksrot) & 3;
            const uint32_t kb = ks * 16;
            uint32_t ah[2][4], al[2][4], bh[NB][4], bl[NB][4];
            #pragma unroll
            for (int mt = 0; mt < 2; ++mt) {
                uint32_t off = SWZ((aRow + mt * 16) * 128 + (kb + aKof) * 2);
                ldsm4(ah[mt], aHi + off);
                if (t3) ldsm4(al[mt], aLo + off);
            }
            #pragma unroll
            for (int bp = 0; bp < NB; ++bp) {
                uint32_t off = SWZ((bRowBase + bp * 16) * 128 + (kb + bKof) * 2);
                ldsm4(bh[bp], bHi + off);
                ldsm4(bl[bp], bLo + off);
            }
            #pragma unroll
            for (int bp = 0; bp < NB; ++bp)
                #pragma unroll
                for (int mt = 0; mt < 2; ++mt) {
                    mma16816(acc[mt][2 * bp],     ah[mt], bh[bp]);
                    mma16816(acc[mt][2 * bp + 1], ah[mt], bh[bp] + 2);
                }
            if (t3) {
                #pragma unroll
                for (int bp = 0; bp < NB; ++bp)
                    #pragma unroll
                    for (int mt = 0; mt < 2; ++mt) {
                        mma16816(acc[mt][2 * bp],     al[mt], bh[bp]);
                        mma16816(acc[mt][2 * bp + 1], al[mt], bh[bp] + 2);
                    }
            }
            #pragma unroll
            for (int bp = 0; bp < NB; ++bp)
                #pragma unroll
                for (int mt = 0; mt < 2; ++mt) {
                    mma16816(acc[mt][2 * bp],     ah[mt], bl[bp]);
                    mma16816(acc[mt][2 * bp + 1], ah[mt], bl[bp] + 2);
                }
        }
        if (c + 1 < nc) { CPWAIT0(); __syncthreads(); }
    }

    // epilogue
    const int g = lane >> 2, tg = lane & 3;
    #pragma unroll
    for (int mt = 0; mt < 2; ++mt) {
        #pragma unroll
        for (int hf = 0; hf < 2; ++hf) {
            int m = m0 + wm + mt * 16 + g + hf * 8;
            float bm = (flags & FBM) ? bias[m] : 0.f;
            long long rbase = (long long)m * ldo;
            #pragma unroll
            for (int nt = 0; nt < NTW; ++nt) {
                int n = n0 + wn + nt * 8 + tg * 2;
                float v0 = alpha * acc[mt][nt][hf * 2 + 0];
                float v1 = alpha * acc[mt][nt][hf * 2 + 1];
                if (flags & FBN) { v0 += bias[n]; v1 += bias[n + 1]; }
                else if (flags & FBM) { v0 += bm; v1 += bm; }
                if (flags & FGELU) {
                    v0 = 0.5f * v0 * (1.f + erff(v0 * 0.70710678118654752f));
                    v1 = 0.5f * v1 * (1.f + erff(v1 * 0.70710678118654752f));
                }
                if (flags & FADD) { v0 += out[rbase + n]; v1 += out[rbase + n + 1]; }
                if (flags & (FOUT | FADD)) { out[rbase + n] = v0; out[rbase + n + 1] = v1; }
                if (flags & FSPL) {
                    u16 h0, l0, h1, l1;
                    splitf(v0, h0, l0);
                    splitf(v1, h1, l1);
                    oh[rbase + n] = h0; ol[rbase + n] = l0;
                    oh[rbase + n + 1] = h1; ol[rbase + n + 1] = l1;
                }
            }
        }
    }
}

// ---------------- reductions ----------------
__device__ __forceinline__ float blockReduceSum(float v) {
    __shared__ float sm[32];
    int lane = threadIdx.x & 31, wid = threadIdx.x >> 5;
    #pragma unroll
    for (int o = 16; o; o >>= 1) v += __shfl_xor_sync(0xffffffffu, v, o);
    if (lane == 0) sm[wid] = v;
    __syncthreads();
    if (wid == 0) {
        int nw = (blockDim.x + 31) >> 5;
        v = (lane < nw) ? sm[lane] : 0.f;
        #pragma unroll
        for (int o = 16; o; o >>= 1) v += __shfl_xor_sync(0xffffffffu, v, o);
        if (lane == 0) sm[0] = v;
    }
    __syncthreads();
    float r = sm[0];
    __syncthreads();
    return r;
}
__device__ __forceinline__ float blockReduceMax(float v) {
    __shared__ float sm[32];
    int lane = threadIdx.x & 31, wid = threadIdx.x >> 5;
    #pragma unroll
    for (int o = 16; o; o >>= 1) v = fmaxf(v, __shfl_xor_sync(0xffffffffu, v, o));
    if (lane == 0) sm[wid] = v;
    __syncthreads();
    if (wid == 0) {
        int nw = (blockDim.x + 31) >> 5;
        v = (lane < nw) ? sm[lane] : -INFINITY;
        #pragma unroll
        for (int o = 16; o; o >>= 1) v = fmaxf(v, __shfl_xor_sync(0xffffffffu, v, o));
        if (lane == 0) sm[0] = v;
    }
    __syncthreads();
    float r = sm[0];
    __syncthreads();
    return r;
}

// groupnorm: writes split output TRANSPOSED: gnT[b][t][c]
__global__ void groupnorm_kernel(const float* __restrict__ x, const float* __restrict__ sc,
                                 const float* __restrict__ bi,
                                 u16* __restrict__ oh, u16* __restrict__ ol) {
    const int CPG = Cc / 32;
    int b = blockIdx.x >> 5, g = blockIdx.x & 31;
    const long long base = ((long long)b * Cc + (long long)g * CPG) * Tt;
    const float* xp = x + base;
    const int n = CPG * Tt;
    float s = 0.f, ss = 0.f;
    for (int i = threadIdx.x; i < n; i += blockDim.x) {
        float v = xp[i]; s += v; ss = fmaf(v, v, ss);
    }
    s = blockReduceSum(s); ss = blockReduceSum(ss);
    float mean = s / n;
    float inv = rsqrtf(ss / n - mean * mean + 1e-6f);
    const long long obase = (long long)b * Tt * Cc + g * CPG;
    for (int j = threadIdx.x; j < n; j += blockDim.x) {
        int t = j / CPG, cc2 = j - t * CPG;
        float v = (xp[(long long)cc2 * Tt + t] - mean) * inv * sc[g * CPG + cc2] + bi[g * CPG + cc2];
        u16 hv, lv; splitf(v, hv, lv);
        long long o = obase + (long long)t * Cc + cc2;
        oh[o] = hv; ol[o] = lv;
    }
}

__global__ void layernorm_kernel(const float* __restrict__ x, const float* __restrict__ sc,
                                 const float* __restrict__ bi,
                                 u16* __restrict__ oh, u16* __restrict__ ol) {
    const long long rb = (long long)blockIdx.x * Ii;
    const float* row = x + rb;
    float s = 0.f, ss = 0.f;
    for (int i = threadIdx.x; i < Ii; i += blockDim.x) {
        float v = row[i]; s += v; ss = fmaf(v, v, ss);
    }
    s = blockReduceSum(s); ss = blockReduceSum(ss);
    float mean = s / (float)Ii;
    float inv = rsqrtf(ss / (float)Ii - mean * mean + 1e-5f);
    for (int i = threadIdx.x; i < Ii; i += blockDim.x) {
        float v = (row[i] - mean) * inv * sc[i] + bi[i];
        u16 hv, lv; splitf(v, hv, lv);
        oh[rb + i] = hv; ol[rb + i] = lv;
    }
}

// small fp32 gemm for tiny cross-attn K/V projections (M=32)
__global__ void __launch_bounds__(256) gemm_kernel(
    const float* __restrict__ A, const float* __restrict__ B, float* __restrict__ Cp,
    int M, int N, int K, int lda, int ldb, int ldc)
{
    __shared__ float As[16][65];
    __shared__ float Bs[16][65];
    int n0 = blockIdx.x * 64, m0 = blockIdx.y * 64;
    int tid = threadIdx.x;
    int tx = tid & 15, ty = tid >> 4;
    float acc[4][4] = {};
    for (int k0 = 0; k0 < K; k0 += 16) {
        #pragma unroll
        for (int u = 0; u < 4; ++u) {
            int i = tid + u * 256;
            int mm = i >> 4, kk = i & 15;
            int m = m0 + mm, k = k0 + kk;
            As[kk][mm] = (m < M && k < K) ? A[(long long)m * lda + k] : 0.f;
        }
        #pragma unroll
        for (int u = 0; u < 4; ++u) {
            int i = tid + u * 256;
            int kk = i >> 6, nn = i & 63;
            int k = k0 + kk, n = n0 + nn;
            Bs[kk][nn] = (k < K && n < N) ? B[(long long)k * ldb + n] : 0.f;
        }
        __syncthreads();
        #pragma unroll
        for (int kk = 0; kk < 16; ++kk) {
            float a[4], bb[4];
            #pragma unroll
            for (int i = 0; i < 4; ++i) a[i] = As[kk][ty * 4 + i];
            #pragma unroll
            for (int j = 0; j < 4; ++j) bb[j] = Bs[kk][tx * 4 + j];
            #pragma unroll
            for (int i = 0; i < 4; ++i)
                #pragma unroll
                for (int j = 0; j < 4; ++j)
                    acc[i][j] = fmaf(a[i], bb[j], acc[i][j]);
        }
        __syncthreads();
    }
    #pragma unroll
    for (int i = 0; i < 4; ++i) {
        int m = m0 + ty * 4 + i;
        if (m >= M) continue;
        #pragma unroll
        for (int j = 0; j < 4; ++j) {
            int n = n0 + tx * 4 + j;
            if (n < N) Cp[(long long)m * ldc + n] = acc[i][j];
        }
    }
}

// softmax: writes bf16 HI only (P is in [0,1]; lo dropped, P*V uses 2-term MMA)
__global__ void softmax_kernel(const float* __restrict__ s, u16* __restrict__ oh) {
    const long long rb = (long long)blockIdx.x * Tt;
    const float* row = s + rb;
    int tid = threadIdx.x;
    float v[8];
    float mx = -INFINITY;
    #pragma unroll
    for (int i = 0; i < 8; ++i) { v[i] = row[tid + (i << 8)]; mx = fmaxf(mx, v[i]); }
    mx = blockReduceMax(mx);
    float sum = 0.f;
    #pragma unroll
    for (int i = 0; i < 8; ++i) { v[i] = expf(v[i] - mx); sum += v[i]; }
    sum = blockReduceSum(sum);
    float inv = 1.f / sum;
    #pragma unroll
    for (int i = 0; i < 8; ++i)
        oh[rb + tid + (i << 8)] = __bfloat16_as_ushort(__float2bfloat16(v[i] * inv));
}

__global__ void crossattn_kernel(const float* __restrict__ q, const float* __restrict__ kc,
                                 const float* __restrict__ vc,
                                 u16* __restrict__ oh, u16* __restrict__ ol) {
    int gw = blockIdx.x * (blockDim.x >> 5) + (threadIdx.x >> 5);
    int lane = threadIdx.x & 31;
    int t = gw % Tt;
    int rem = gw / Tt;
    int h = rem % Hh;
    int b = rem / Hh;
    const float* qp = q + ((long long)(b * Tt + t)) * Ii + h * Dh;
    const float* kb = kc + (long long)b * Ss * Ii + h * Dh;
    const float* vb = vc + (long long)b * Ss * Ii + h * Dh;
    float sj = -INFINITY;
    if (lane < Ss) {
        const float* kp = kb + lane * Ii;
        float acc = 0.f;
        #pragma unroll
        for (int d2 = 0; d2 < Dh; ++d2) acc = fmaf(qp[d2], kp[d2], acc);
        sj = acc * 0.125f;
    }
    float mx = sj;
    #pragma unroll
    for (int o = 16; o; o >>= 1) mx = fmaxf(mx, __shfl_xor_sync(0xffffffffu, mx, o));
    float p = (lane < Ss) ? expf(sj - mx) : 0.f;
    float sum = p;
    #pragma unroll
    for (int o = 16; o; o >>= 1) sum += __shfl_xor_sync(0xffffffffu, sum, o);
    p /= sum;
    float o0 = 0.f, o1 = 0.f;
    #pragma unroll
    for (int j = 0; j < Ss; ++j) {
        float pj = __shfl_sync(0xffffffffu, p, j);
        const float* vp = vb + j * Ii;
        o0 = fmaf(pj, vp[lane], o0);
        o1 = fmaf(pj, vp[lane + 32], o1);
    }
    long long ob = ((long long)(b * Tt + t)) * Ii + h * Dh;
    u16 hv, lv;
    splitf(o0, hv, lv); oh[ob + lane] = hv; ol[ob + lane] = lv;
    splitf(o1, hv, lv); oh[ob + lane + 32] = hv; ol[ob + lane + 32] = lv;
}

// per-head transpose of split V (src row stride ld, col offset off)
__global__ void transposeV_kernel(const u16* __restrict__ vh, const u16* __restrict__ vl,
                                  u16* __restrict__ oth, u16* __restrict__ otl,
                                  int ld, int off) {
    __shared__ u16 th[32][33], tl[32][33];
    int bh = blockIdx.z;
    int b = bh / Hh, h = bh % Hh;
    int t0 = blockIdx.x * 32, d0 = blockIdx.y * 32;
    #pragma unroll
    for (int i = 0; i < 32; i += 8) {
        long long src = ((long long)(b * Tt + t0 + threadIdx.y + i)) * ld + off + h * Dh + d0 + threadIdx.x;
        th[threadIdx.y + i][threadIdx.x] = vh[src];
        tl[threadIdx.y + i][threadIdx.x] = vl[src];
    }
    __syncthreads();
    #pragma unroll
    for (int i = 0; i < 32; i += 8) {
        long long dst = ((long long)((b * Hh + h) * Dh + d0 + threadIdx.y + i)) * Tt + t0 + threadIdx.x;
        oth[dst] = th[threadIdx.x][threadIdx.y + i];
        otl[dst] = tl[threadIdx.x][threadIdx.y + i];
    }
}

// elementwise split fp32 -> bf16 hi/lo
__global__ void split_ew(const float* __restrict__ w, u16* __restrict__ oh,
                         u16* __restrict__ ol, long long n) {
    long long i = (long long)blockIdx.x * 256 + threadIdx.x;
    if (i >= n) return;
    u16 hv, lv; splitf(w[i], hv, lv);
    oh[i] = hv; ol[i] = lv;
}

// transpose 768x768 [K][N] -> [N][K] + split
__global__ void splitT768(const float* __restrict__ w, u16* __restrict__ oh,
                          u16* __restrict__ ol) {
    __shared__ float t[32][33];
    int k0 = blockIdx.y * 32, n0 = blockIdx.x * 32;
    #pragma unroll
    for (int i = 0; i < 32; i += 8)
        t[threadIdx.y + i][threadIdx.x] = w[(long long)(k0 + threadIdx.y + i) * Ii + n0 + threadIdx.x];
    __syncthreads();
    #pragma unroll
    for (int i = 0; i < 32; i += 8) {
        long long o = (long long)(n0 + threadIdx.y + i) * Ii + k0 + threadIdx.x;
        u16 hv, lv; splitf(t[threadIdx.x][threadIdx.y + i], hv, lv);
        oh[o] = hv; ol[o] = lv;
    }
}

// conv weight reorder+split: out[o][k*Cin+c] = in[o][c*Ksz+k]
__global__ void reorder_split(const float* __restrict__ w, u16* __restrict__ oh,
                              u16* __restrict__ ol, long long total, int Cin) {
    long long i = (long long)blockIdx.x * 256 + threadIdx.x;
    if (i >= total) return;
    int rk = Cin * Ksz;
    long long oc = i / rk;
    int r = (int)(i - oc * rk);
    int k = r / Cin, c = r - k * Cin;
    u16 hv, lv; splitf(w[oc * rk + (long long)c * Ksz + k], hv, lv);
    oh[i] = hv; ol[i] = lv;
}

// ---------------- host wrapper ----------------
static void tc(const u16* Ah, const u16* Al, const u16* Bh, const u16* Bl,
               const float* bias, float* out, u16* oh, u16* ol,
               int gx, int gy, int gz, int K, int lda, int ldb, long long ldo,
               int flags, float alpha, long long offA, long long flimA,
               int b2, long long sA1, long long sA2, long long sB1, long long sB2,
               long long sC1, long long sC2, int terms = 3)
{
    dim3 g(gx, gy, gz);
    tc_gemm<<<g, NTHREADS, TC_SMEM>>>(Ah, Al, Bh, Bl, bias, out, oh, ol, K, lda, ldb,
        ldo, flags, alpha, offA, flimA, b2, sA1, sA2, sB1, sB2, sC1, sC2, terms);
}

extern "C" void kernel_launch(void* const* d_in, const int* in_sizes, int n_in,
                              void* d_out, int out_size) {
    const float* x      = (const float*)d_in[0];
    const float* ctx    = (const float*)d_in[1];
    const float* gn_s   = (const float*)d_in[2];
    const float* gn_b   = (const float*)d_in[3];
    const float* pin_w  = (const float*)d_in[4];
    const float* pin_b  = (const float*)d_in[5];
    const float* n1_s   = (const float*)d_in[6];
    const float* n1_b   = (const float*)d_in[7];
    const float* a1_wq  = (const float*)d_in[8];
    const float* a1_wk  = (const float*)d_in[9];
    const float* a1_wv  = (const float*)d_in[10];
    const float* a1_wo  = (const float*)d_in[11];
    const float* a1_bo  = (const float*)d_in[12];
    const float* n2_s   = (const float*)d_in[13];
    const float* n2_b   = (const float*)d_in[14];
    const float* a2_wq  = (const float*)d_in[15];
    const float* a2_wk  = (const float*)d_in[16];
    const float* a2_wv  = (const float*)d_in[17];
    const float* a2_wo  = (const float*)d_in[18];
    const float* a2_bo  = (const float*)d_in[19];
    const float* n3_s   = (const float*)d_in[20];
    const float* n3_b   = (const float*)d_in[21];
    const float* ff1_w  = (const float*)d_in[22];
    const float* ff1_b  = (const float*)d_in[23];
    const float* ff2_w  = (const float*)d_in[24];
    const float* ff2_b  = (const float*)d_in[25];
    const float* pout_w = (const float*)d_in[26];
    const float* pout_b = (const float*)d_in[27];
    float* out = (float*)d_out;

    cudaFuncSetAttribute(tc_gemm, cudaFuncAttributeMaxDynamicSharedMemorySize, TC_SMEM);

    float *h, *q, *sc, *kcb, *vcb;
    u16 *gnh, *gnl, *yh, *yl, *qkvh, *qkvl, *vth_, *vtl_, *ath, *atl;
    u16 *hh, *hl, *ph, *pl, *ffh, *ffl, *w1h, *w1l, *w2h, *w2l, *wth, *wtl;
    cudaGetSymbolAddress((void**)&h,   g_h);
    cudaGetSymbolAddress((void**)&q,   g_q);
    cudaGetSymbolAddress((void**)&sc,  g_sc);
    cudaGetSymbolAddress((void**)&kcb, g_kc);
    cudaGetSymbolAddress((void**)&vcb, g_vc);
    cudaGetSymbolAddress((void**)&gnh, g_gnh); cudaGetSymbolAddress((void**)&gnl, g_gnl);
    cudaGetSymbolAddress((void**)&yh,  g_yh);  cudaGetSymbolAddress((void**)&yl,  g_yl);
    cudaGetSymbolAddress((void**)&qkvh, g_qkvh); cudaGetSymbolAddress((void**)&qkvl, g_qkvl);
    cudaGetSymbolAddress((void**)&vth_, g_vth); cudaGetSymbolAddress((void**)&vtl_, g_vtl);
    cudaGetSymbolAddress((void**)&ath, g_ath); cudaGetSymbolAddress((void**)&atl, g_atl);
    cudaGetSymbolAddress((void**)&hh,  g_hh);  cudaGetSymbolAddress((void**)&hl,  g_hl);
    cudaGetSymbolAddress((void**)&ph,  g_ph);  cudaGetSymbolAddress((void**)&pl,  g_pl);
    cudaGetSymbolAddress((void**)&ffh, g_ffh); cudaGetSymbolAddress((void**)&ffl, g_ffl);
    cudaGetSymbolAddress((void**)&w1h, g_w1h); cudaGetSymbolAddress((void**)&w1l, g_w1l);
    cudaGetSymbolAddress((void**)&w2h, g_w2h); cudaGetSymbolAddress((void**)&w2l, g_w2l);
    cudaGetSymbolAddress((void**)&wth, g_wth); cudaGetSymbolAddress((void**)&wtl, g_wtl);

    const long long BIG = 1LL << 62;
    const long long TI = (long long)Tt * Ii;
    const long long T3I = (long long)Tt * 3 * Ii;
    const long long WSZ = (long long)Ii * Ii;
    const unsigned WB = (unsigned)((WSZ + 255) / 256);

    split_ew<<<WB, 256>>>(pin_w,  wth + 6 * WSZ, wtl + 6 * WSZ, WSZ);
    split_ew<<<WB, 256>>>(pout_w, wth + 7 * WSZ, wtl + 7 * WSZ, WSZ);

    groupnorm_kernel<<<Bb * 32, 256>>>(x, gn_s, gn_b, gnh, gnl);  // writes gnT [b][t][c]

    // proj_in
    tc(gnh, gnl, wth + 6 * WSZ, wtl + 6 * WSZ, pin_b, h, 0, 0,
       Ii / 64, Tt / 128, Bb, Cc, Cc, Cc, Ii, FBN | FOUT, 1.f,
       0, BIG, 1, (long long)Tt * Cc, 0, 0, 0, TI, 0);

    for (int d = 0; d < Dd; ++d) {
        long long wofs = (long long)d * WSZ;
        dim3 tg(24, 24), tb(32, 8);
        splitT768<<<tg, tb>>>(a1_wq + wofs, wth + 0 * WSZ, wtl + 0 * WSZ);
        splitT768<<<tg, tb>>>(a1_wk + wofs, wth + 1 * WSZ, wtl + 1 * WSZ);
        splitT768<<<tg, tb>>>(a1_wv + wofs, wth + 2 * WSZ, wtl + 2 * WSZ);
        splitT768<<<tg, tb>>>(a1_wo + wofs, wth + 3 * WSZ, wtl + 3 * WSZ);
        splitT768<<<tg, tb>>>(a2_wq + wofs, wth + 4 * WSZ, wtl + 4 * WSZ);
        splitT768<<<tg, tb>>>(a2_wo + wofs, wth + 5 * WSZ, wtl + 5 * WSZ);
        {
            long long t1 = (long long)Fi * Ii * Ksz;
            reorder_split<<<(unsigned)((t1 + 255) / 256), 256>>>(ff1_w + d * t1, w1h, w1l, t1, Ii);
            long long t2 = (long long)Ii * Fi * Ksz;
            reorder_split<<<(unsigned)((t2 + 255) / 256), 256>>>(ff2_w + d * t2, w2h, w2l, t2, Fi);
        }

        // --- self attention ---
        layernorm_kernel<<<Bb * Tt, 256>>>(h, n1_s + d * Ii, n1_b + d * Ii, yh, yl);
        // fused QKV
        tc(yh, yl, wth, wtl, 0, sc, qkvh, qkvl, (3 * Ii) / 64, (Bb * Tt) / 128, 1,
           Ii, Ii, Ii, 3 * Ii, FSPL, 1.f, 0, BIG, 1, 0, 0, 0, 0, 0, 0);
        {
            dim3 g(Tt / 32, Dh / 32, Bb * Hh);
            transposeV_kernel<<<g, dim3(32, 8)>>>(qkvh, qkvl, vth_, vtl_, 3 * Ii, 2 * Ii);
        }
        // scores = 0.125 q k^T per (b,h)
        tc(qkvh, qkvl, qkvh + Ii, qkvl + Ii, 0, sc, 0, 0,
           Tt / 64, Tt / 128, Bb * Hh, Dh, 3 * Ii, 3 * Ii, Tt,
           FOUT, 0.125f, 0, BIG, Hh, T3I, Dh, T3I, Dh,
           (long long)Hh * Tt * Tt, (long long)Tt * Tt);
        softmax_kernel<<<Bb * Hh * Tt, 256>>>(sc, ph);
        // att = P @ V per (b,h) — 2-term split (P hi only, V hi+lo)
        tc(ph, pl, vth_, vtl_, 0, sc, ath, atl, 1, Tt / 128, Bb * Hh, Tt, Tt, Tt, Ii,
           FSPL, 1.f, 0, BIG, Hh,
           (long long)Hh * Tt * Tt, (long long)Tt * Tt,
           (long long)Hh * Dh * Tt, (long long)Dh * Tt, TI, Dh, /*terms=*/2);
        // h += att @ wo + bo
        tc(ath, atl, wth + 3 * WSZ, wtl + 3 * WSZ, a1_bo + d * Ii, h, 0, 0,
           Ii / 64, (Bb * Tt) / 128, 1, Ii, Ii, Ii, Ii,
           FBN | FADD, 1.f, 0, BIG, 1, 0, 0, 0, 0, 0, 0);

        // --- cross attention ---
        layernorm_kernel<<<Bb * Tt, 256>>>(h, n2_s + d * Ii, n2_b + d * Ii, yh, yl);
        tc(yh, yl, wth + 4 * WSZ, wtl + 4 * WSZ, 0, q, 0, 0, Ii / 64, (Bb * Tt) / 128, 1,
           Ii, Ii, Ii, Ii, FOUT, 1.f, 0, BIG, 1, 0, 0, 0, 0, 0, 0);
        {
            dim3 g((Ii + 63) / 64, (Bb * Ss + 63) / 64);
            gemm_kernel<<<g, 256>>>(ctx, a2_wk + (long long)d * Cx * Ii, kcb,
                                    Bb * Ss, Ii, Cx, Cx, Ii, Ii);
            gemm_kernel<<<g, 256>>>(ctx, a2_wv + (long long)d * Cx * Ii, vcb,
                                    Bb * Ss, Ii, Cx, Cx, Ii, Ii);
        }
        crossattn_kernel<<<Bb * Hh * Tt / 8, 256>>>(q, kcb, vcb, ath, atl);
        tc(ath, atl, wth + 5 * WSZ, wtl + 5 * WSZ, a2_bo + d * Ii, h, 0, 0,
           Ii / 64, (Bb * Tt) / 128, 1, Ii, Ii, Ii, Ii,
           FBN | FADD, 1.f, 0, BIG, 1, 0, 0, 0, 0, 0, 0);

        // --- feed-forward ---
        layernorm_kernel<<<Bb * Tt, 256>>>(h, n3_s + d * Ii, n3_b + d * Ii, yh, yl);
        tc(yh, yl, w1h, w1l, ff1_b + d * Fi, sc, ffh, ffl, Fi / 64, Tt / 128, Bb,
           Ii * Ksz, Ii, Ii * Ksz, Fi, FBN | FGELU | FSPL, 1.f,
           -(long long)4 * Ii, TI, 1, TI, 0, 0, 0, (long long)Tt * Fi, 0);
        tc(ffh, ffl, w2h, w2l, ff2_b + d * Ii, h, hh, hl, Ii / 64, Tt / 128, Bb,
           Fi * Ksz, Fi, Fi * Ksz, Ii,
           FBN | FADD | (d == Dd - 1 ? FSPL : 0), 1.f,
           -(long long)4 * Fi, (long long)Tt * Fi, 1,
           (long long)Tt * Fi, 0, 0, 0, TI, 0);
    }

    // out = x + pout_w @ h^T + pout_b
    cudaMemcpyAsync(out, x, (size_t)Bb * Cc * Tt * sizeof(float),
                    cudaMemcpyDeviceToDevice);
    tc(wth + 7 * WSZ, wtl + 7 * WSZ, hh, hl, pout_b, out, 0, 0,
       Tt / 64, Cc / 128, Bb, Ii, Ii, Ii, Tt, FBM | FADD, 1.f,
       0, BIG, 1, 0, 0, TI, 0, (long long)Cc * Tt, 0);
}